// round 4
// baseline (speedup 1.0000x reference)
#include <cuda_runtime.h>
#include <cstdint>

#define NN    4096
#define FIN   128
#define NH    8
#define FO    64
#define FTOT  512
#define KT    32
#define NSPL  2
#define JSPL  (NN / NSPL)          // 2048 j per split
#define NKT   (JSPL / KT)          // 64 tiles per split
#define LOG2E 1.4426950408889634f

// ---------------- scratch (static device memory only) ----------------
__device__ float g_ht[NN * FTOT];              // 8 MB: hW flat == ht[h][n][o]
__device__ float g_src[NH * NN];
__device__ float g_tgt[NH * NN];
__device__ unsigned g_Tbits[NH];               // per-head max(tgt), monotonic-uint enc
__device__ unsigned g_adjb[NN * NN / 32];      // 2 MB bit-packed adjacency
__device__ float g_part[NSPL][NH * NN * FO];   // 16 MB split numerators
__device__ float g_psum[NSPL][NH * NN];        // split denominators

// ---------------- helpers ----------------
__device__ __forceinline__ unsigned encf(float f) {
    unsigned b = __float_as_uint(f);
    return (b & 0x80000000u) ? ~b : (b | 0x80000000u);
}
__device__ __forceinline__ float decf(unsigned k) {
    unsigned b = (k & 0x80000000u) ? (k & 0x7FFFFFFFu) : ~k;
    return __uint_as_float(b);
}
__device__ __forceinline__ uint32_t f2tf32(float v) {
    uint32_t u;
    asm("cvt.rna.tf32.f32 %0, %1;" : "=r"(u) : "f"(v));
    return u;
}
__device__ __forceinline__ float ex2f(float x) {
    float r;
    asm("ex2.approx.f32 %0, %1;" : "=f"(r) : "f"(x));
    return r;
}
__device__ __forceinline__ void mma_tf32(float c[4], uint32_t a0, uint32_t a1,
                                         uint32_t a2, uint32_t a3,
                                         uint32_t b0, uint32_t b1) {
    asm volatile(
        "mma.sync.aligned.m16n8k8.row.col.f32.tf32.tf32.f32 "
        "{%0,%1,%2,%3}, {%4,%5,%6,%7}, {%8,%9}, {%0,%1,%2,%3};"
        : "+f"(c[0]), "+f"(c[1]), "+f"(c[2]), "+f"(c[3])
        : "r"(a0), "r"(a1), "r"(a2), "r"(a3), "r"(b0), "r"(b1));
}

// ---------------- kernel A: hW = h @ W  (64x64 tile, 2x8 per thread) ----------------
__global__ void __launch_bounds__(256)
k_gemm(const float* __restrict__ H, const float* __restrict__ W) {
    __shared__ float sA[64][68];
    __shared__ float sW[64][64];
    const int row0 = blockIdx.x * 64, col0 = blockIdx.y * 64, t = threadIdx.x;
    const int r = t >> 3, c0 = (t & 7) * 8;
    float acc[2][8];
#pragma unroll
    for (int i = 0; i < 2; ++i)
#pragma unroll
        for (int c = 0; c < 8; ++c) acc[i][c] = 0.f;

    for (int kk = 0; kk < FIN; kk += 64) {
#pragma unroll
        for (int u = 0; u < 4; ++u) {
            int idx = t + u * 256;            // 1024 f4
            int rr = idx >> 4, q = idx & 15;
            float4 v = *(const float4*)(H + (size_t)(row0 + rr) * FIN + kk + q * 4);
            *(float4*)&sA[rr][q * 4] = v;
        }
#pragma unroll
        for (int u = 0; u < 4; ++u) {
            int idx = t + u * 256;
            int k = idx >> 4, q = idx & 15;
            float4 v = *(const float4*)(W + (size_t)(kk + k) * FTOT + col0 + q * 4);
            *(float4*)&sW[k][q * 4] = v;
        }
        __syncthreads();
#pragma unroll
        for (int k = 0; k < 64; ++k) {
            float a0 = sA[r][k], a1 = sA[r + 32][k];
            float4 w0 = *(float4*)&sW[k][c0];
            float4 w1 = *(float4*)&sW[k][c0 + 4];
            const float wv[8] = { w0.x, w0.y, w0.z, w0.w, w1.x, w1.y, w1.z, w1.w };
#pragma unroll
            for (int c = 0; c < 8; ++c) {
                acc[0][c] = fmaf(a0, wv[c], acc[0][c]);
                acc[1][c] = fmaf(a1, wv[c], acc[1][c]);
            }
        }
        __syncthreads();
    }
    float* o1 = g_ht + (size_t)(row0 + r) * FTOT + col0 + c0;
    float* o2 = g_ht + (size_t)(row0 + r + 32) * FTOT + col0 + c0;
    *(float4*)(o1)     = make_float4(acc[0][0], acc[0][1], acc[0][2], acc[0][3]);
    *(float4*)(o1 + 4) = make_float4(acc[0][4], acc[0][5], acc[0][6], acc[0][7]);
    *(float4*)(o2)     = make_float4(acc[1][0], acc[1][1], acc[1][2], acc[1][3]);
    *(float4*)(o2 + 4) = make_float4(acc[1][4], acc[1][5], acc[1][6], acc[1][7]);
}

// ---------------- bit-pack adjacency (+ init g_Tbits) ----------------
__global__ void k_pack(const int* __restrict__ adj) {
    if (blockIdx.x == 0 && threadIdx.x < NH) g_Tbits[threadIdx.x] = 0u;
    const int lane = threadIdx.x & 31;
    const int gw = (blockIdx.x * blockDim.x + threadIdx.x) >> 5;
    const int nwarps = (gridDim.x * blockDim.x) >> 5;
    const int NW = NN * NN / 32;
    for (int w = gw; w < NW; w += nwarps) {
        int v = adj[(size_t)w * 32 + lane];
        unsigned m = __ballot_sync(0xFFFFFFFFu, v != 0);
        if (lane == 0) g_adjb[w] = m;
    }
}

// ---------------- src/tgt projections + fused per-head max ----------------
__global__ void k_srctgt(const float* __restrict__ a) {
    const int warp = threadIdx.x >> 5, lane = threadIdx.x & 31;
    const int gw = blockIdx.x * 8 + warp;
    const int h = gw >> 12;
    const int n = gw & (NN - 1);
    const float* htp = g_ht + (size_t)h * (NN * FO) + (size_t)n * FO;
    float v0 = htp[lane], v1 = htp[lane + 32];
    float a0 = a[h * 128 + lane],      a1 = a[h * 128 + lane + 32];
    float b0 = a[h * 128 + 64 + lane], b1 = a[h * 128 + 96 + lane];
    float s  = v0 * a0 + v1 * a1;
    float tg = v0 * b0 + v1 * b1;
#pragma unroll
    for (int off = 16; off; off >>= 1) {
        s  += __shfl_down_sync(0xFFFFFFFFu, s, off);
        tg += __shfl_down_sync(0xFFFFFFFFu, tg, off);
    }
    if (lane == 0) {
        g_src[h * NN + n] = s;
        g_tgt[h * NN + n] = tg;
        atomicMax(&g_Tbits[h], encf(tg));
    }
}

// ---------------- kernel C: fused masked-softmax @ V  (m32n64 per warp, split-K) ----------------
// block = (head, 128-row i-tile, k-split). 4 warps; warp w owns rows w*32..w*32+31
// as two m16 groups. B = V tile (32k x 64n) double-buffered; b-fragments shared
// by both row groups (halved LDS). Writes split-partial numerator + denominator.
__global__ void __launch_bounds__(128, 4)
k_attn_mma(const unsigned* __restrict__ adjb, float* __restrict__ part,
           float* __restrict__ psums) {
    __shared__ float sV[2][KT][72];
    __shared__ float sTgt[2][KT];

    const int head  = blockIdx.x;
    const int ibase = blockIdx.y * 128;
    const int spl   = blockIdx.z;
    const int jbase = spl * JSPL;
    const int t     = threadIdx.x;
    const int wid   = t >> 5;
    const int lane  = t & 31;
    const int g     = lane >> 2;
    const int tg4   = lane & 3;

    const int rbase = ibase + wid * 32 + g;   // rows rbase + {0,8,16,24}

    float src[4], mm[4];
    const float Th = decf(g_Tbits[head]);
#pragma unroll
    for (int rg = 0; rg < 4; ++rg) {
        src[rg] = g_src[head * NN + rbase + rg * 8];
        float e0 = src[rg] + Th;
        mm[rg] = fmaxf(e0, 0.2f * e0) * LOG2E;     // >= scaled row max
    }
    const unsigned* arow[4];
#pragma unroll
    for (int rg = 0; rg < 4; ++rg)
        arow[rg] = adjb + (size_t)(rbase + rg * 8) * (NN / 32) + (jbase / 32);

    const float* tgtp = g_tgt + head * NN + jbase;
    const float* vp   = g_ht + (size_t)head * (NN * FO) + (size_t)jbase * FO;

    float acc[2][8][4];
#pragma unroll
    for (int gr = 0; gr < 2; ++gr)
#pragma unroll
        for (int nb = 0; nb < 8; ++nb)
#pragma unroll
            for (int q = 0; q < 4; ++q) acc[gr][nb][q] = 0.f;
    float psum[4] = { 0.f, 0.f, 0.f, 0.f };

    auto load_tile = [&](int kt, int s) {
#pragma unroll
        for (int u = 0; u < 4; ++u) {
            int idx = t + u * 128;              // 512 f4 per tile
            int k = idx >> 4, q = idx & 15;
            float4 v = *(const float4*)(vp + (size_t)(kt * KT + k) * FO + q * 4);
            uint4 r;
            r.x = f2tf32(v.x); r.y = f2tf32(v.y);
            r.z = f2tf32(v.z); r.w = f2tf32(v.w);
            *(uint4*)&sV[s][k][q * 4] = r;
        }
        if (t < KT) sTgt[s][t] = tgtp[kt * KT + t];
    };

    load_tile(0, 0);

    for (int kt = 0; kt < NKT; ++kt) {
        const int s = kt & 1;
        __syncthreads();
        if (kt + 1 < NKT) load_tile(kt + 1, s ^ 1);

        unsigned wbits[4];
#pragma unroll
        for (int rg = 0; rg < 4; ++rg) wbits[rg] = arow[rg][kt];

#pragma unroll
        for (int ks = 0; ks < 4; ++ks) {
            const int c1 = ks * 8 + tg4;
            const int c2 = c1 + 4;
            const float tgv1 = sTgt[s][c1];
            const float tgv2 = sTgt[s][c2];

            uint32_t aw[4][2];                  // [rg][col-half]
#pragma unroll
            for (int rg = 0; rg < 4; ++rg) {
                float e1 = src[rg] + tgv1;
                float l1 = fmaxf(e1, 0.2f * e1);
                float w1 = ((wbits[rg] >> c1) & 1u) ? ex2f(fmaf(l1, LOG2E, -mm[rg])) : 0.f;
                float e2 = src[rg] + tgv2;
                float l2 = fmaxf(e2, 0.2f * e2);
                float w2 = ((wbits[rg] >> c2) & 1u) ? ex2f(fmaf(l2, LOG2E, -mm[rg])) : 0.f;
                aw[rg][0] = f2tf32(w1);
                aw[rg][1] = f2tf32(w2);
                psum[rg] += __uint_as_float(aw[rg][0]) + __uint_as_float(aw[rg][1]);
            }
#pragma unroll
            for (int nb = 0; nb < 8; ++nb) {
                uint32_t b0 = __float_as_uint(sV[s][c1][nb * 8 + g]);
                uint32_t b1 = __float_as_uint(sV[s][c2][nb * 8 + g]);
                mma_tf32(acc[0][nb], aw[0][0], aw[1][0], aw[0][1], aw[1][1], b0, b1);
                mma_tf32(acc[1][nb], aw[2][0], aw[3][0], aw[2][1], aw[3][1], b0, b1);
            }
        }
    }

    // denominator partials: sum the 4 lanes of each quad
#pragma unroll
    for (int rg = 0; rg < 4; ++rg) {
        psum[rg] += __shfl_xor_sync(0xFFFFFFFFu, psum[rg], 1);
        psum[rg] += __shfl_xor_sync(0xFFFFFFFFu, psum[rg], 2);
    }
    float* psp = psums + (size_t)spl * (NH * NN) + head * NN;
    if (tg4 == 0) {
#pragma unroll
        for (int rg = 0; rg < 4; ++rg)
            psp[rbase + rg * 8] = psum[rg];
    }

    // numerator partials
    float* pp = part + (size_t)spl * (NH * NN * FO) + ((size_t)head * NN) * FO;
#pragma unroll
    for (int gr = 0; gr < 2; ++gr) {
        float* o1 = pp + (size_t)(rbase + gr * 16) * FO + 2 * tg4;
        float* o2 = o1 + 8 * FO;
#pragma unroll
        for (int nb = 0; nb < 8; ++nb) {
            *(float2*)(o1 + nb * 8) = make_float2(acc[gr][nb][0], acc[gr][nb][1]);
            *(float2*)(o2 + nb * 8) = make_float2(acc[gr][nb][2], acc[gr][nb][3]);
        }
    }
}

// ---------------- combine splits ----------------
__global__ void k_comb(float* __restrict__ out) {
    const int idx = blockIdx.x * blockDim.x + threadIdx.x;   // f4 index
    const int row = idx >> 4;                                // (h*NN + i)
    float4 n0 = *(const float4*)(&g_part[0][(size_t)idx * 4]);
    float4 n1 = *(const float4*)(&g_part[1][(size_t)idx * 4]);
    float s = g_psum[0][row] + g_psum[1][row];
    float inv = (s > 0.f) ? 1.0f / s : 0.f;
    float4 o;
    o.x = (n0.x + n1.x) * inv;
    o.y = (n0.y + n1.y) * inv;
    o.z = (n0.z + n1.z) * inv;
    o.w = (n0.w + n1.w) * inv;
    *(float4*)(out + (size_t)idx * 4) = o;
}

// ---------------- host launcher ----------------
extern "C" void kernel_launch(void* const* d_in, const int* in_sizes, int n_in,
                              void* d_out, int out_size) {
    const float* H = nullptr; const int* adj = nullptr;
    const float* W = nullptr; const float* a = nullptr;
    for (int i = 0; i < n_in; ++i) {
        switch (in_sizes[i]) {
            case NN * FIN:    H   = (const float*)d_in[i]; break;
            case NN * NN:     adj = (const int*)d_in[i];   break;
            case FIN * FTOT:  W   = (const float*)d_in[i]; break;
            case NH * 2 * FO: a   = (const float*)d_in[i]; break;
        }
    }
    float* out = (float*)d_out;

    unsigned* adjb; cudaGetSymbolAddress((void**)&adjb, g_adjb);
    float* part;    cudaGetSymbolAddress((void**)&part, g_part);
    float* psums;   cudaGetSymbolAddress((void**)&psums, g_psum);

    k_gemm    <<<dim3(NN / 64, FTOT / 64), 256>>>(H, W);
    k_pack    <<<512, 256>>>(adj);
    k_srctgt  <<<(NN * NH) / 8, 256>>>(a);
    k_attn_mma<<<dim3(NH, NN / 128, NSPL), 128>>>(adjb, part, psums);
    k_comb    <<<(NH * NN * FO / 4) / 256, 256>>>(out);
}

// round 5
// speedup vs baseline: 1.2615x; 1.2615x over previous
#include <cuda_runtime.h>
#include <cstdint>

#define NN    4096
#define FIN   128
#define NH    8
#define FO    64
#define FTOT  512
#define KT    64
#define NSPL  2
#define JSPL  (NN / NSPL)          // 2048 j per split
#define NKT   (JSPL / KT)          // 32 tiles per split
#define LOG2E 1.4426950408889634f

// ---------------- scratch (static device memory only) ----------------
__device__ float g_ht[NN * FTOT];              // 8 MB: hW flat == ht[h][n][o]
__device__ float g_src[NH * NN];
__device__ float g_tgt[NH * NN];
__device__ unsigned g_Tbits[NH];               // per-head max(tgt), monotonic enc
__device__ unsigned g_adjb[NN * NN / 32];      // 2 MB bit-packed adjacency
__device__ float4 g_tp[NH * (NN / 8) * 4];     // 256 KB: {L[c],L[c+4],T02[c],T02[c+4]}
__device__ float g_part[NSPL][NH * NN * FO];   // 16 MB split numerators
__device__ float g_psum[NSPL][NH * NN];        // split denominators

// ---------------- helpers ----------------
__device__ __forceinline__ unsigned encf(float f) {
    unsigned b = __float_as_uint(f);
    return (b & 0x80000000u) ? ~b : (b | 0x80000000u);
}
__device__ __forceinline__ float decf(unsigned k) {
    unsigned b = (k & 0x80000000u) ? (k & 0x7FFFFFFFu) : ~k;
    return __uint_as_float(b);
}
__device__ __forceinline__ float ex2f(float x) {
    float r;
    asm("ex2.approx.f32 %0, %1;" : "=f"(r) : "f"(x));
    return r;
}
__device__ __forceinline__ unsigned long long pack2(float x, float y) {
    unsigned long long r;
    asm("mov.b64 %0, {%1, %2};" : "=l"(r) : "f"(x), "f"(y));
    return r;
}
__device__ __forceinline__ void unpack2(unsigned long long v, float& x, float& y) {
    asm("mov.b64 {%0, %1}, %2;" : "=f"(x), "=f"(y) : "l"(v));
}
__device__ __forceinline__ unsigned long long add2(unsigned long long a,
                                                   unsigned long long b) {
    unsigned long long d;
    asm("add.rn.f32x2 %0, %1, %2;" : "=l"(d) : "l"(a), "l"(b));
    return d;
}
__device__ __forceinline__ unsigned long long ffma2(unsigned long long a,
                                                    unsigned long long b,
                                                    unsigned long long c) {
    unsigned long long d;
    asm("fma.rn.f32x2 %0, %1, %2, %3;" : "=l"(d) : "l"(a), "l"(b), "l"(c));
    return d;
}
__device__ __forceinline__ uint32_t smem_u32(const void* p) {
    uint32_t a;
    asm("{ .reg .u64 t; cvta.to.shared.u64 t, %1; cvt.u32.u64 %0, t; }"
        : "=r"(a) : "l"(p));
    return a;
}
__device__ __forceinline__ void cp16(uint32_t dst, const void* src) {
    asm volatile("cp.async.cg.shared.global [%0], [%1], 16;"
                 :: "r"(dst), "l"(src) : "memory");
}
__device__ __forceinline__ void cp_commit() {
    asm volatile("cp.async.commit_group;" ::: "memory");
}
__device__ __forceinline__ void mma_tf32(float c[4], uint32_t a0, uint32_t a1,
                                         uint32_t a2, uint32_t a3,
                                         uint32_t b0, uint32_t b1) {
    asm volatile(
        "mma.sync.aligned.m16n8k8.row.col.f32.tf32.tf32.f32 "
        "{%0,%1,%2,%3}, {%4,%5,%6,%7}, {%8,%9}, {%0,%1,%2,%3};"
        : "+f"(c[0]), "+f"(c[1]), "+f"(c[2]), "+f"(c[3])
        : "r"(a0), "r"(a1), "r"(a2), "r"(a3), "r"(b0), "r"(b1));
}

// ---------------- kernel A: hW = h @ W  (64x64 tile, packed f32x2) ----------------
__global__ void __launch_bounds__(256)
k_gemm(const float* __restrict__ H, const float* __restrict__ W) {
    __shared__ float sA[64][68];
    __shared__ float sW[64][64];
    const int row0 = blockIdx.x * 64, col0 = blockIdx.y * 64, t = threadIdx.x;
    const int r = t >> 3, c0 = (t & 7) * 8;
    unsigned long long accP[2][4];
#pragma unroll
    for (int i = 0; i < 2; ++i)
#pragma unroll
        for (int p = 0; p < 4; ++p) accP[i][p] = 0ull;

    for (int kk = 0; kk < FIN; kk += 64) {
#pragma unroll
        for (int u = 0; u < 4; ++u) {
            int idx = t + u * 256;
            int rr = idx >> 4, q = idx & 15;
            float4 v = *(const float4*)(H + (size_t)(row0 + rr) * FIN + kk + q * 4);
            *(float4*)&sA[rr][q * 4] = v;
        }
#pragma unroll
        for (int u = 0; u < 4; ++u) {
            int idx = t + u * 256;
            int k = idx >> 4, q = idx & 15;
            float4 v = *(const float4*)(W + (size_t)(kk + k) * FTOT + col0 + q * 4);
            *(float4*)&sW[k][q * 4] = v;
        }
        __syncthreads();
#pragma unroll
        for (int k = 0; k < 64; ++k) {
            unsigned long long a0P = pack2(sA[r][k], sA[r][k]);
            unsigned long long a1P = pack2(sA[r + 32][k], sA[r + 32][k]);
            const unsigned long long* wP = (const unsigned long long*)&sW[k][c0];
#pragma unroll
            for (int p = 0; p < 4; ++p) {
                accP[0][p] = ffma2(a0P, wP[p], accP[0][p]);
                accP[1][p] = ffma2(a1P, wP[p], accP[1][p]);
            }
        }
        __syncthreads();
    }
#pragma unroll
    for (int i = 0; i < 2; ++i) {
        float* o = g_ht + (size_t)(row0 + r + i * 32) * FTOT + col0 + c0;
#pragma unroll
        for (int p = 0; p < 4; ++p) {
            float x, y;
            unpack2(accP[i][p], x, y);
            o[2 * p] = x; o[2 * p + 1] = y;
        }
    }
}

// ---------------- bit-pack adjacency (+ init g_Tbits) ----------------
__global__ void k_pack(const int* __restrict__ adj) {
    if (blockIdx.x == 0 && threadIdx.x < NH) g_Tbits[threadIdx.x] = 0u;
    const int lane = threadIdx.x & 31;
    const int gw = (blockIdx.x * blockDim.x + threadIdx.x) >> 5;
    const int nwarps = (gridDim.x * blockDim.x) >> 5;
    const int NW = NN * NN / 32;
    for (int w = gw; w < NW; w += nwarps) {
        int v = adj[(size_t)w * 32 + lane];
        unsigned m = __ballot_sync(0xFFFFFFFFu, v != 0);
        if (lane == 0) g_adjb[w] = m;
    }
}

// ---------------- src/tgt projections + fused per-head max ----------------
__global__ void k_srctgt(const float* __restrict__ a) {
    const int warp = threadIdx.x >> 5, lane = threadIdx.x & 31;
    const int gw = blockIdx.x * 8 + warp;
    const int h = gw >> 12;
    const int n = gw & (NN - 1);
    const float* htp = g_ht + (size_t)h * (NN * FO) + (size_t)n * FO;
    float v0 = htp[lane], v1 = htp[lane + 32];
    float a0 = a[h * 128 + lane],      a1 = a[h * 128 + lane + 32];
    float b0 = a[h * 128 + 64 + lane], b1 = a[h * 128 + 96 + lane];
    float s  = v0 * a0 + v1 * a1;
    float tg = v0 * b0 + v1 * b1;
#pragma unroll
    for (int off = 16; off; off >>= 1) {
        s  += __shfl_down_sync(0xFFFFFFFFu, s, off);
        tg += __shfl_down_sync(0xFFFFFFFFu, tg, off);
    }
    if (lane == 0) {
        g_src[h * NN + n] = s;
        g_tgt[h * NN + n] = tg;
        atomicMax(&g_Tbits[h], encf(tg));
    }
}

// ---------------- prep: pairwise (tgt*L, 0.2*L*tgt) table ----------------
__global__ void k_prep() {
    const int idx = blockIdx.x * 256 + threadIdx.x;     // 16384
    const int h = idx >> 11;
    const int bq = idx & 2047;
    const int b = bq >> 2, q = bq & 3;
    const float* tp = g_tgt + h * NN + b * 8;
    float t1 = tp[q], t2 = tp[q + 4];
    g_tp[idx] = make_float4(t1 * LOG2E, t2 * LOG2E,
                            t1 * (0.2f * LOG2E), t2 * (0.2f * LOG2E));
}

// ---------------- kernel C: fused masked-softmax @ V ----------------
// block = (head, 128-row i-tile, k-split); 4 warps, m32 rows each.
// KT=64 j-tile, cp.async double buffer. Denominator via ones-column (nb=8).
// No tf32 cvt: HMMA truncates; num/den consume identical truncated weights.
__global__ void __launch_bounds__(128, 4)
k_attn_mma(const unsigned* __restrict__ adjb, float* __restrict__ part,
           float* __restrict__ psums) {
    __shared__ float sV[2][KT][72];
    __shared__ float4 sTgtP[2][32];

    const int head  = blockIdx.x;
    const int ibase = blockIdx.y * 128;
    const int spl   = blockIdx.z;
    const int jbase = spl * JSPL;
    const int t     = threadIdx.x;
    const int wid   = t >> 5;
    const int lane  = t & 31;
    const int g     = lane >> 2;
    const int tg4   = lane & 3;

    const int rbase = ibase + wid * 32 + g;       // rows rbase + {0,8,16,24}

    const float Th = decf(g_Tbits[head]);
    unsigned long long srcP[4], src02P[4];
#pragma unroll
    for (int rg = 0; rg < 4; ++rg) {
        float src = g_src[head * NN + rbase + rg * 8];
        float e0 = src + Th;
        float mm = fmaxf(e0, 0.2f * e0) * LOG2E;  // >= scaled row max
        float sL   = src * LOG2E - mm;
        float sL02 = src * (0.2f * LOG2E) - mm;
        srcP[rg]   = pack2(sL, sL);
        src02P[rg] = pack2(sL02, sL02);
    }

    const unsigned* abase = adjb + (size_t)rbase * (NN / 32) + (jbase / 32);
    const float* vp = g_ht + (size_t)head * (NN * FO) + (size_t)jbase * FO;
    const float4* tpp = g_tp + (size_t)head * (NN / 8) * 4 + (size_t)(jbase / 8) * 4;

    const uint32_t svb = smem_u32(&sV[0][0][0]);
    const uint32_t stb = smem_u32(&sTgtP[0][0]);

    // pad columns: col 64 = 1 (denominator), 65..71 = 0. Written once.
    for (int idx = t; idx < 2 * KT * 8; idx += 128) {
        int s = idx >> 9, r = (idx >> 3) & 63, cc = idx & 7;
        sV[s][r][64 + cc] = (cc == 0) ? 1.0f : 0.0f;
    }

    float acc[2][9][4];
#pragma unroll
    for (int gr = 0; gr < 2; ++gr)
#pragma unroll
        for (int nb = 0; nb < 9; ++nb)
#pragma unroll
            for (int q = 0; q < 4; ++q) acc[gr][nb][q] = 0.f;

    auto load_tile = [&](int kt, int s) {
        const float* base = vp + (size_t)kt * KT * FO;
        const uint32_t sb = svb + (uint32_t)s * (KT * 72 * 4);
#pragma unroll
        for (int u = 0; u < 8; ++u) {
            int idx = t + u * 128;            // 1024 16B chunks
            int r = idx >> 4, q = idx & 15;
            cp16(sb + (uint32_t)r * 288 + (uint32_t)q * 16,
                 base + (size_t)r * FO + q * 4);
        }
        if (t < 32)
            cp16(stb + (uint32_t)s * 512 + (uint32_t)t * 16, tpp + kt * 32 + t);
        cp_commit();
    };

    load_tile(0, 0);

    for (int kt = 0; kt < NKT; ++kt) {
        const int s = kt & 1;
        if (kt + 1 < NKT) {
            load_tile(kt + 1, s ^ 1);
            asm volatile("cp.async.wait_group 1;" ::: "memory");
        } else {
            asm volatile("cp.async.wait_group 0;" ::: "memory");
        }
        __syncthreads();

        unsigned long long wb[4];
#pragma unroll
        for (int rg = 0; rg < 4; ++rg) {
            uint2 w2 = *(const uint2*)(abase + (size_t)rg * 8 * (NN / 32) + 2 * kt);
            wb[rg] = (unsigned long long)w2.x | ((unsigned long long)w2.y << 32);
        }

#pragma unroll
        for (int ks = 0; ks < 8; ++ks) {
            const float4 tq = sTgtP[s][ks * 4 + tg4];
            const unsigned long long tLP  = pack2(tq.x, tq.y);
            const unsigned long long t02P = pack2(tq.z, tq.w);
            const int c1 = ks * 8 + tg4;

            uint32_t aw[4][2];
#pragma unroll
            for (int rg = 0; rg < 4; ++rg) {
                unsigned long long t1 = add2(srcP[rg], tLP);
                unsigned long long t2 = add2(src02P[rg], t02P);
                float x1, y1, x2, y2;
                unpack2(t1, x1, y1);
                unpack2(t2, x2, y2);
                float w1 = ex2f(fmaxf(x1, x2));
                float w2 = ex2f(fmaxf(y1, y2));
                unsigned bs = (unsigned)(wb[rg] >> c1);
                w1 = (bs & 1u)  ? w1 : 0.0f;
                w2 = (bs & 16u) ? w2 : 0.0f;
                aw[rg][0] = __float_as_uint(w1);
                aw[rg][1] = __float_as_uint(w2);
            }
#pragma unroll
            for (int nb = 0; nb < 9; ++nb) {
                uint32_t b0 = __float_as_uint(sV[s][c1][nb * 8 + g]);
                uint32_t b1 = __float_as_uint(sV[s][c1 + 4][nb * 8 + g]);
                mma_tf32(acc[0][nb], aw[0][0], aw[1][0], aw[0][1], aw[1][1], b0, b1);
                mma_tf32(acc[1][nb], aw[2][0], aw[3][0], aw[2][1], aw[3][1], b0, b1);
            }
        }
        __syncthreads();
    }

    // ---- denominator partials (ones-column lives at tg4==0, col offset 0) ----
    float* psp = psums + (size_t)spl * (NH * NN) + head * NN;
    if (tg4 == 0) {
        psp[rbase]      = acc[0][8][0];
        psp[rbase + 8]  = acc[0][8][2];
        psp[rbase + 16] = acc[1][8][0];
        psp[rbase + 24] = acc[1][8][2];
    }

    // ---- numerator partials ----
    float* pp = part + (size_t)spl * (NH * NN * FO) + ((size_t)head * NN) * FO;
#pragma unroll
    for (int gr = 0; gr < 2; ++gr) {
        float* o1 = pp + (size_t)(rbase + gr * 16) * FO + 2 * tg4;
        float* o2 = o1 + 8 * FO;
#pragma unroll
        for (int nb = 0; nb < 8; ++nb) {
            *(float2*)(o1 + nb * 8) = make_float2(acc[gr][nb][0], acc[gr][nb][1]);
            *(float2*)(o2 + nb * 8) = make_float2(acc[gr][nb][2], acc[gr][nb][3]);
        }
    }
}

// ---------------- combine splits ----------------
__global__ void k_comb(float* __restrict__ out) {
    const int idx = blockIdx.x * blockDim.x + threadIdx.x;   // f4 index
    const int row = idx >> 4;                                // (h*NN + i)
    float4 n0 = *(const float4*)(&g_part[0][(size_t)idx * 4]);
    float4 n1 = *(const float4*)(&g_part[1][(size_t)idx * 4]);
    float s = g_psum[0][row] + g_psum[1][row];
    float inv = (s > 0.f) ? 1.0f / s : 0.f;
    float4 o;
    o.x = (n0.x + n1.x) * inv;
    o.y = (n0.y + n1.y) * inv;
    o.z = (n0.z + n1.z) * inv;
    o.w = (n0.w + n1.w) * inv;
    *(float4*)(out + (size_t)idx * 4) = o;
}

// ---------------- host launcher ----------------
extern "C" void kernel_launch(void* const* d_in, const int* in_sizes, int n_in,
                              void* d_out, int out_size) {
    const float* H = nullptr; const int* adj = nullptr;
    const float* W = nullptr; const float* a = nullptr;
    for (int i = 0; i < n_in; ++i) {
        switch (in_sizes[i]) {
            case NN * FIN:    H   = (const float*)d_in[i]; break;
            case NN * NN:     adj = (const int*)d_in[i];   break;
            case FIN * FTOT:  W   = (const float*)d_in[i]; break;
            case NH * 2 * FO: a   = (const float*)d_in[i]; break;
        }
    }
    float* out = (float*)d_out;

    unsigned* adjb; cudaGetSymbolAddress((void**)&adjb, g_adjb);
    float* part;    cudaGetSymbolAddress((void**)&part, g_part);
    float* psums;   cudaGetSymbolAddress((void**)&psums, g_psum);

    k_gemm    <<<dim3(NN / 64, FTOT / 64), 256>>>(H, W);
    k_pack    <<<512, 256>>>(adj);
    k_srctgt  <<<(NN * NH) / 8, 256>>>(a);
    k_prep    <<<64, 256>>>();
    k_attn_mma<<<dim3(NH, NN / 128, NSPL), 128>>>(adjb, part, psums);
    k_comb    <<<(NH * NN * FO / 4) / 256, 256>>>(out);
}